// round 2
// baseline (speedup 1.0000x reference)
#include <cuda_runtime.h>

// RNN-T transducer loss forward. B=16, T=200, U=101, A=512, blank=0.
//
// Kernel 1 (gather): full-chip, pulls blk = lp[...,0] and emit = lp[...,label]
//   into compact padded scratch [B][T][104] (2.6MB, L2-resident). 4 cells/thread.
// Kernel 2 (lattice+reduce): 16 CTAs, 128 threads, barrier-free anti-diagonal
//   wavefront. Thread u owns column u. Intra-warp u-1 dependency via shfl_up;
//   cross-warp boundary via packed (step,value) 64-bit volatile smem handoff.
//   Last CTA (atomic counter) does the fixed-order mean reduction.

#define BQ 16
#define TM 200
#define UM 101
#define AA 512
#define UP 104      // padded U: float4-aligned; diagonal stride -103 is odd -> conflict-free
#define SMAXCAP 304

__device__ __align__(16) float g_blk [BQ][TM][UP];
__device__ __align__(16) float g_emit[BQ][TM][UP];
__device__ float g_logp[BQ];
__device__ int   g_cnt = 0;

__global__ void tl_gather_kernel(const float* __restrict__ lp,
                                 const int*   __restrict__ labels)
{
    const int total  = BQ * TM * UM;
    const int stride = gridDim.x * blockDim.x;
    int i0 = blockIdx.x * blockDim.x + threadIdx.x;
    #pragma unroll
    for (int k = 0; k < 4; ++k) {
        int i = i0 + k * stride;
        if (i < total) {
            int u  = i % UM;
            int bt = i / UM;
            int t  = bt % TM;
            int b  = bt / TM;
            int lab = (u < UM - 1) ? __ldg(labels + b * (UM - 1) + u) : 0;
            size_t base = (size_t)i * AA;           // i == ((b*TM + t)*UM + u)
            float bv = __ldg(lp + base);            // blank channel
            float ev = lab ? __ldg(lp + base + lab) : bv;
            g_blk [b][t][u] = bv;
            g_emit[b][t][u] = ev;
        }
    }
}

__device__ __forceinline__ float lae(float x, float y)
{
    float m = fmaxf(x, y);
    float d = fminf(x, y) - m;                      // <= 0, finite
    return m + __logf(1.0f + __expf(d));
}

__global__ __launch_bounds__(128, 1)
void tl_lattice_kernel(const int* __restrict__ Tarr,
                       const int* __restrict__ Uarr,
                       float* __restrict__ out)
{
    extern __shared__ float sm[];
    float* s_blk  = sm;                             // [TM][UP]
    float* s_emit = sm + TM * UP;                   // [TM][UP]
    __shared__ unsigned long long s_h[3][SMAXCAP];  // warp w writes row w; warp w+1 reads

    const int b    = blockIdx.x;
    const int tid  = threadIdx.x;
    const int lane = tid & 31;
    const int w    = tid >> 5;

    // Stage compact blk/emit for this batch into shared (coalesced float4).
    {
        const float4* gb = (const float4*)&g_blk [b][0][0];
        const float4* ge = (const float4*)&g_emit[b][0][0];
        float4* sb4 = (float4*)s_blk;
        float4* se4 = (float4*)s_emit;
        const int n4 = TM * UP / 4;                 // 5200
        for (int k = tid; k < n4; k += 128) {
            sb4[k] = gb[k];
            se4[k] = ge[k];
        }
    }
    // Zero the handoff slots.
    for (int k = tid; k < 3 * SMAXCAP; k += 128)
        ((unsigned long long*)s_h)[k] = 0ULL;

    const int Tb = __ldg(Tarr + b);
    const int Ub = __ldg(Uarr + b);
    __syncthreads();

    const int u    = tid;
    const int smax = (Tb - 1) + Ub;                 // final step: cell (Tb-1, Ub)
    const float em0 = (u > 0) ? s_emit[u - 1] : 0.0f;   // emit[t=0, u-1] (hoisted)
    float own = 0.0f;                               // this thread's alpha at previous step

    volatile unsigned long long* hrow_r = (w > 0) ? &s_h[w - 1][0] : 0;
    volatile unsigned long long* hrow_w = (w < 3) ? &s_h[w][0]     : 0;
    const bool is_writer = (lane == 31) && (w < 3);

    for (int s = 0; s <= smax; ++s) {
        const int t = s - u;
        const bool active = ((unsigned)t < (unsigned)Tb) && (u <= Ub);

        // Issue smem loads early (clamped so inactive lanes stay in-bounds).
        int tc = t;
        if (tc < 1) tc = 1;
        if (tc > TM - 1) tc = TM - 1;
        const float blkv = s_blk[(tc - 1) * UP + u];
        const float emv  = (u > 0) ? s_emit[tc * UP + (u - 1)] : 0.0f;

        // Horizontal dependency: neighbor's alpha at step s-1.
        float hor = __shfl_up_sync(0xffffffffu, own, 1);
        if (lane == 0 && w > 0 && active) {
            // Need thread u-1 (prev warp, lane 31) value from step s-1;
            // writer packs ((s-1)+1) in the high word.
            volatile unsigned long long* p = hrow_r + (s - 1);
            unsigned long long v = *p;
            while ((unsigned)(v >> 32) != (unsigned)s) v = *p;
            hor = __uint_as_float((unsigned)v);
        }

        if (active) {
            float val;
            if (t == 0) {
                val = (u == 0) ? 0.0f : hor + em0;
            } else if (u == 0) {
                val = own + blkv;
            } else {
                val = lae(own + blkv, hor + emv);
            }
            own = val;
            if (t == Tb - 1 && u == Ub) {
                // log_p = alpha[T-1,U] + blk[T-1,U]
                g_logp[b] = val + s_blk[(Tb - 1) * UP + Ub];
            }
        }

        if (is_writer) {
            hrow_w[s] = ((unsigned long long)(unsigned)(s + 1) << 32)
                        | (unsigned long long)__float_as_uint(own);
        }
    }

    // Fixed-order mean reduction in the last-arriving CTA (deterministic).
    __syncthreads();
    if (tid == 0) {
        __threadfence();
        int old = atomicAdd(&g_cnt, 1);
        if (old == BQ - 1) {
            __threadfence();
            float ssum = 0.0f;
            #pragma unroll
            for (int i = 0; i < BQ; ++i) ssum += g_logp[i];
            out[0] = -ssum / (float)BQ;
            g_cnt = 0;                              // reset for next graph replay
        }
    }
}

extern "C" void kernel_launch(void* const* d_in, const int* in_sizes, int n_in,
                              void* d_out, int out_size)
{
    const float* lp     = (const float*)d_in[0];
    const int*   labels = (const int*)  d_in[1];
    const int*   Tarr   = (const int*)  d_in[2];
    const int*   Uarr   = (const int*)  d_in[3];
    float* out = (float*)d_out;

    const int smem_bytes = 2 * TM * UP * (int)sizeof(float);   // 166,400
    cudaFuncSetAttribute(tl_lattice_kernel,
                         cudaFuncAttributeMaxDynamicSharedMemorySize,
                         smem_bytes);

    const int total  = BQ * TM * UM;                // 323,200
    const int blocks = (total + 256 * 4 - 1) / (256 * 4);      // 316
    tl_gather_kernel<<<blocks, 256>>>(lp, labels);
    tl_lattice_kernel<<<BQ, 128, smem_bytes>>>(Tarr, Uarr, out);
}

// round 4
// speedup vs baseline: 1.7021x; 1.7021x over previous
#include <cuda_runtime.h>

// RNN-T transducer loss forward. B=16, T=200, U=101, A=512, blank=0.
// Log-domain (proven-exact) anti-diagonal wavefront, branchless inner loop.
//
//  K1 gather: full-chip; blk = lp[...,0], emS[t][u] = lp[b,t,u-1,label[u-1]]
//     (emit shifted +1 so cell u reads column u), into [B][T][104] scratch.
//  K2 lattice: 16 CTAs x 128 threads. Stage 166KB into smem. Thread u owns
//     column u; step s computes cell (t=s-u, u):
//       alpha[t,u] = logaddexp(own + blk[t-1,u], edge[u-1] + emS[t,u])
//     Edge double-buffered in smem; slot 0 pinned to -1e30 so u==0 needs no
//     branch (logaddexp(ver,-1e30)==ver exactly). Capture after the loop.
//     Fixed-order mean reduction in the last-arriving CTA.

#define BQ 16
#define TM 200
#define UM 101
#define AA 512
#define UP 104          // padded row width (float4 aligned)
#define NEG (-1.0e30f)

__device__ __align__(16) float g_blk[BQ][TM][UP];
__device__ __align__(16) float g_em [BQ][TM][UP];  // shifted: [t][u] = emit[t][u-1]; [t][0]=0
__device__ float g_logp[BQ];
__device__ int   g_cnt = 0;

__global__ void tl_gather_kernel(const float* __restrict__ lp,
                                 const int*   __restrict__ labels)
{
    const int total  = BQ * TM * UM;
    const int stride = gridDim.x * blockDim.x;
    int i0 = blockIdx.x * blockDim.x + threadIdx.x;
    #pragma unroll
    for (int kk = 0; kk < 4; ++kk) {
        int i = i0 + kk * stride;
        if (i < total) {
            int u  = i % UM;
            int bt = i / UM;
            int t  = bt % TM;
            int b  = bt / TM;
            int lab = (u < UM - 1) ? __ldg(labels + b * (UM - 1) + u) : 0;
            size_t base = (size_t)i * AA;          // i == ((b*TM + t)*UM + u)
            float bv = __ldg(lp + base);           // blank log-prob
            float ev = lab ? __ldg(lp + base + lab) : bv;
            g_blk[b][t][u]     = bv;
            g_em [b][t][u + 1] = ev;               // shifted by +1
            if (u == 0) g_em[b][t][0] = 0.0f;
            if (u == UM - 1) {                     // zero pad columns
                g_blk[b][t][101] = 0.f; g_blk[b][t][102] = 0.f; g_blk[b][t][103] = 0.f;
                g_em [b][t][102] = 0.f; g_em [b][t][103] = 0.f;
            }
        }
    }
}

__global__ __launch_bounds__(128, 1)
void tl_lattice_kernel(const int* __restrict__ Tarr,
                       const int* __restrict__ Uarr,
                       float* __restrict__ out)
{
    extern __shared__ float sm[];
    float* s_blk = sm;                 // [TM][UP]
    float* s_em  = sm + TM * UP;       // [TM][UP]
    __shared__ float s_edge[2][132];   // slot u+1 <- thread u; slot 0 stays NEG

    const int b   = blockIdx.x;
    const int tid = threadIdx.x;

    // Stage blk/em for this batch into shared (coalesced float4).
    {
        const float4* gb = (const float4*)&g_blk[b][0][0];
        const float4* ge = (const float4*)&g_em [b][0][0];
        float4* sb = (float4*)s_blk;
        float4* se = (float4*)s_em;
        const int n4 = TM * UP / 4;    // 5200
        for (int k = tid; k < n4; k += 128) { sb[k] = gb[k]; se[k] = ge[k]; }
    }
    for (int k = tid; k < 2 * 132; k += 128)
        ((float*)s_edge)[k] = NEG;

    const int Tb = __ldg(Tarr + b);
    const int Ub = __ldg(Uarr + b);
    __syncthreads();

    const int u    = tid;              // threads 0..103 own real columns
    const int smax = (Tb - 1) + Ub;
    float own = 0.0f;

    for (int s = 0; s <= smax; ++s) {
        const int w = s & 1;
        const int r = w ^ 1;
        const int t = s - u;
        const bool act = ((unsigned)t < (unsigned)Tb);
        const int tc  = min(max(t, 0), Tb - 1);
        const int tc1 = min(max(t, 1), Tb - 1);

        const float hin  = s_edge[r][u];               // alpha[t][u-1] (or NEG for u==0)
        const float emv  = s_em [ tc       * UP + u];  // emit[t][u-1] (shifted layout)
        const float blkv = s_blk[(tc1 - 1) * UP + u];  // blk[t-1][u]

        const float ver = own + blkv;
        const float hor = hin + emv;
        // logaddexp(ver, hor); exact pass-through when hor == NEG
        const float m  = fmaxf(ver, hor);
        const float d  = fminf(ver, hor) - m;
        const float lv = m + __logf(1.0f + __expf(d));

        const float val = (t == 0) ? ((u == 0) ? 0.0f : hor) : lv;
        own = act ? val : own;
        s_edge[w][u + 1] = val;
        __syncthreads();
    }

    // log_p = alpha[Tb-1][Ub] + blk[Tb-1][Ub]
    if (u == Ub) g_logp[b] = own + s_blk[(Tb - 1) * UP + Ub];
    __syncthreads();

    // Fixed-order mean reduction in the last-arriving CTA (deterministic).
    if (tid == 0) {
        __threadfence();
        int old = atomicAdd(&g_cnt, 1);
        if (old == BQ - 1) {
            __threadfence();
            float ssum = 0.0f;
            #pragma unroll
            for (int i = 0; i < BQ; ++i) ssum += g_logp[i];
            out[0] = -ssum / (float)BQ;
            g_cnt = 0;                 // reset for next graph replay
        }
    }
}

extern "C" void kernel_launch(void* const* d_in, const int* in_sizes, int n_in,
                              void* d_out, int out_size)
{
    const float* lp     = (const float*)d_in[0];
    const int*   labels = (const int*)  d_in[1];
    const int*   Tarr   = (const int*)  d_in[2];
    const int*   Uarr   = (const int*)  d_in[3];
    float* out = (float*)d_out;

    const int smem_bytes = 2 * TM * UP * (int)sizeof(float);   // 166,400
    cudaFuncSetAttribute(tl_lattice_kernel,
                         cudaFuncAttributeMaxDynamicSharedMemorySize,
                         smem_bytes);

    const int total  = BQ * TM * UM;                           // 323,200
    const int blocks = (total + 256 * 4 - 1) / (256 * 4);      // 316
    tl_gather_kernel<<<blocks, 256>>>(lp, labels);
    tl_lattice_kernel<<<BQ, 128, smem_bytes>>>(Tarr, Uarr, out);
}